// round 4
// baseline (speedup 1.0000x reference)
#include <cuda_runtime.h>
#include <cstdint>

// Problem constants (fixed shapes)
#define B_  4
#define H_  160
#define W_  160
#define NF_ 64
#define HW_ (H_ * W_)
#define OC_ 216   // 3 * DG * KK
#define DG_ 8
#define KK_ 9
#define SLOPE_ 0.1f

// ---------------------------------------------------------------------------
// Scratch buffers (static device globals; no runtime allocation allowed)
// ---------------------------------------------------------------------------
__device__ float g_bufA[B_ * NF_ * HW_];   // 26.2 MB
__device__ float g_bufB[B_ * NF_ * HW_];   // 26.2 MB
__device__ float g_co  [B_ * OC_ * HW_];   // 88.5 MB
__device__ float g_feat[B_ * NF_ * HW_];   // 26.2 MB

// ---------------------------------------------------------------------------
// Direct 3x3 conv, NCHW, stride 1, pad 1.
//  - Input is one or two 64-channel tensors (channel concat when CIN==128).
//  - Block computes a 16x16 output tile x COUT_BLK channels for one image.
//  - 256 threads: 8x8 "pixel quads" (each thread owns 2x2 pixels) x 4 channel
//    groups (each thread owns NCPT = COUT_BLK/4 output channels).
//  - Loops over input channels in chunks of CK=8, staging an 18x18xCK input
//    tile and the CKx9xCOUT_BLK weight slice in shared memory.
//  - Outer loops deliberately NOT fully unrolled (compile time / I$ size).
// ---------------------------------------------------------------------------
template <int CIN, int COUT_BLK>
__global__ __launch_bounds__(256)
void conv3x3_k(const float* __restrict__ in0, const float* __restrict__ in1,
               const float* __restrict__ wgt, const float* __restrict__ bias,
               float* __restrict__ out, int cout_total, int act)
{
    constexpr int CK   = 8;
    constexpr int NCH  = CIN / CK;
    constexpr int NCPT = COUT_BLK / 4;

    __shared__ float s_in[CK * 18 * 19];           // [ck][18 rows][19 stride]
    __shared__ float s_w [CK * 9 * COUT_BLK];      // [(ck*9+tap)][cout]

    const int tid = threadIdx.x;
    const int nz  = gridDim.z / B_;
    const int b   = blockIdx.z / nz;
    const int zb  = blockIdx.z - b * nz;
    const int cout_off = zb * COUT_BLK;

    const int cg  = tid >> 6;          // channel group 0..3
    const int t   = tid & 63;
    const int ty2 = (t >> 3) * 2;      // 0..14 step 2
    const int tx2 = (t & 7) * 2;       // 0..14 step 2

    const int by = blockIdx.y * 16;
    const int bx = blockIdx.x * 16;

    float acc[2][2][NCPT];
#pragma unroll
    for (int yy = 0; yy < 2; ++yy)
#pragma unroll
        for (int xx = 0; xx < 2; ++xx)
#pragma unroll
            for (int c = 0; c < NCPT; ++c) acc[yy][xx][c] = 0.f;

#pragma unroll 1
    for (int ch = 0; ch < NCH; ++ch) {
        const int cin0 = ch * CK;

        // ---- stage input tile (18x18xCK, zero-padded at borders) ----
#pragma unroll 1
        for (int i = tid; i < CK * 18 * 18; i += 256) {
            const int ck = i / 324;
            const int r  = i - ck * 324;
            const int yy = r / 18;
            const int xx = r - yy * 18;
            const int gy = by + yy - 1;
            const int gx = bx + xx - 1;
            const int c  = cin0 + ck;
            float v = 0.f;
            if (gy >= 0 && gy < H_ && gx >= 0 && gx < W_) {
                if (CIN == 128 && c >= 64)
                    v = in1[(((size_t)b * 64 + (c - 64)) * H_ + gy) * W_ + gx];
                else
                    v = in0[(((size_t)b * 64 + c) * H_ + gy) * W_ + gx];
            }
            s_in[(ck * 18 + yy) * 19 + xx] = v;
        }
        // ---- stage weights ----
#pragma unroll 1
        for (int i = tid; i < CK * 9 * COUT_BLK; i += 256) {
            const int co = i % COUT_BLK;
            const int rt = i / COUT_BLK;          // ck*9 + tap
            const int ck = rt / 9;
            const int tap = rt - ck * 9;
            s_w[i] = wgt[((size_t)(cout_off + co) * CIN + (cin0 + ck)) * 9 + tap];
        }
        __syncthreads();

        // ---- compute ----
#pragma unroll 2
        for (int ck = 0; ck < CK; ++ck) {
            float xr[4][4];
#pragma unroll
            for (int yy = 0; yy < 4; ++yy)
#pragma unroll
                for (int xx = 0; xx < 4; ++xx)
                    xr[yy][xx] = s_in[(ck * 18 + ty2 + yy) * 19 + tx2 + xx];

#pragma unroll
            for (int ky = 0; ky < 3; ++ky)
#pragma unroll
                for (int kx = 0; kx < 3; ++kx) {
                    const float* wrow =
                        &s_w[(ck * 9 + ky * 3 + kx) * COUT_BLK + cg * NCPT];
#pragma unroll
                    for (int c = 0; c < NCPT; ++c) {
                        const float wv = wrow[c];
                        acc[0][0][c] = fmaf(xr[ky    ][kx    ], wv, acc[0][0][c]);
                        acc[0][1][c] = fmaf(xr[ky    ][kx + 1], wv, acc[0][1][c]);
                        acc[1][0][c] = fmaf(xr[ky + 1][kx    ], wv, acc[1][0][c]);
                        acc[1][1][c] = fmaf(xr[ky + 1][kx + 1], wv, acc[1][1][c]);
                    }
                }
        }
        __syncthreads();
    }

    // ---- bias + activation + store ----
#pragma unroll
    for (int c = 0; c < NCPT; ++c) {
        const int co = cout_off + cg * NCPT + c;
        const float bv = bias[co];
#pragma unroll
        for (int yy = 0; yy < 2; ++yy)
#pragma unroll
            for (int xx = 0; xx < 2; ++xx) {
                float v = acc[yy][xx][c] + bv;
                if (act) v = (v > 0.f) ? v : SLOPE_ * v;
                out[(((size_t)b * cout_total + co) * H_ + (by + ty2 + yy)) * W_
                    + (bx + tx2 + xx)] = v;
            }
    }
}

// ---------------------------------------------------------------------------
// Modulated deformable conv (DCNv2Pack apply stage).
//  co: [B, 216, H, W] = (144 interleaved (dg,k,{y,x}) offsets, 72 mask logits)
//  Each thread owns one output pixel, all 64 output channels.
//  Per deform-group g: stage w[:, g*8:(g+1)*8, :, :] as [k][c][o] in SMEM
//  (all-thread broadcast reads), bilinear-gather the 8 group channels, and
//  rank-1 update the 64 accumulators.
// ---------------------------------------------------------------------------
__global__ __launch_bounds__(256)
void dcn_k(const float* __restrict__ xin, const float* __restrict__ co,
           const float* __restrict__ wgt, const float* __restrict__ bias,
           float* __restrict__ out, int act)
{
    __shared__ float s_wg[KK_ * 8 * 64];   // 18.4 KB

    const int tid = threadIdx.x;
    const int b   = blockIdx.z;
    const int y   = blockIdx.y * 16 + (tid >> 4);
    const int x   = blockIdx.x * 16 + (tid & 15);

    float acc[64];
#pragma unroll
    for (int o = 0; o < 64; ++o) acc[o] = 0.f;

    const float* cob = co + (size_t)b * OC_ * HW_;
    const int pix = y * W_ + x;

#pragma unroll 1
    for (int g = 0; g < DG_; ++g) {
        __syncthreads();
#pragma unroll 1
        for (int i = tid; i < KK_ * 8 * 64; i += 256) {
            const int o = i & 63;
            const int r = i >> 6;          // k*8 + c
            const int k = r >> 3;
            const int c = r & 7;
            s_wg[i] = wgt[((size_t)o * 64 + g * 8 + c) * KK_ + k];
        }
        __syncthreads();

        const float* xb = xin + ((size_t)b * 64 + g * 8) * HW_;

#pragma unroll 1
        for (int k = 0; k < KK_; ++k) {
            const float offy = cob[(size_t)(g * 18 + 2 * k    ) * HW_ + pix];
            const float offx = cob[(size_t)(g * 18 + 2 * k + 1) * HW_ + pix];
            const float ml   = cob[(size_t)(144 + g * 9 + k   ) * HW_ + pix];
            const float m    = 1.f / (1.f + __expf(-ml));

            const float py = (float)y + (float)(k / 3 - 1) + offy;
            const float px = (float)x + (float)(k % 3 - 1) + offx;
            const float y0f = floorf(py), x0f = floorf(px);
            const float ly = py - y0f,  lx = px - x0f;
            const int y0 = (int)y0f,    x0 = (int)x0f;

            const float w00 = (1.f - ly) * (1.f - lx) * m;
            const float w01 = (1.f - ly) * lx * m;
            const float w10 = ly * (1.f - lx) * m;
            const float w11 = ly * lx * m;

            const bool iy0 = (y0 >= 0)     && (y0 < H_);
            const bool iy1 = (y0 + 1 >= 0) && (y0 + 1 < H_);
            const bool ix0 = (x0 >= 0)     && (x0 < W_);
            const bool ix1 = (x0 + 1 >= 0) && (x0 + 1 < W_);

            const int p00 = y0 * W_ + x0;

#pragma unroll
            for (int c = 0; c < 8; ++c) {
                const float* xc = xb + (size_t)c * HW_;
                float s = 0.f;
                if (iy0 && ix0) s = fmaf(w00, __ldg(xc + p00),          s);
                if (iy0 && ix1) s = fmaf(w01, __ldg(xc + p00 + 1),      s);
                if (iy1 && ix0) s = fmaf(w10, __ldg(xc + p00 + W_),     s);
                if (iy1 && ix1) s = fmaf(w11, __ldg(xc + p00 + W_ + 1), s);

                const float4* wr = (const float4*)&s_wg[(k * 8 + c) * 64];
#pragma unroll
                for (int o4 = 0; o4 < 16; ++o4) {
                    const float4 w4 = wr[o4];
                    acc[o4 * 4 + 0] = fmaf(s, w4.x, acc[o4 * 4 + 0]);
                    acc[o4 * 4 + 1] = fmaf(s, w4.y, acc[o4 * 4 + 1]);
                    acc[o4 * 4 + 2] = fmaf(s, w4.z, acc[o4 * 4 + 2]);
                    acc[o4 * 4 + 3] = fmaf(s, w4.w, acc[o4 * 4 + 3]);
                }
            }
        }
    }

#pragma unroll
    for (int o = 0; o < 64; ++o) {
        float v = acc[o] + bias[o];
        if (act) v = (v > 0.f) ? v : SLOPE_ * v;
        out[(((size_t)b * 64 + o) * H_ + y) * W_ + x] = v;
    }
}

// ---------------------------------------------------------------------------
// Launch
// ---------------------------------------------------------------------------
extern "C" void kernel_launch(void* const* d_in, const int* in_sizes, int n_in,
                              void* d_out, int out_size)
{
    const float* nbr     = (const float*)d_in[0];
    const float* ref     = (const float*)d_in[1];
    const float* w_off1  = (const float*)d_in[2];
    const float* b_off1  = (const float*)d_in[3];
    const float* w_off2  = (const float*)d_in[4];
    const float* b_off2  = (const float*)d_in[5];
    const float* w_co    = (const float*)d_in[6];
    const float* b_co    = (const float*)d_in[7];
    const float* w_dcn   = (const float*)d_in[8];
    const float* b_dcn   = (const float*)d_in[9];
    const float* w_coff1 = (const float*)d_in[10];
    const float* b_coff1 = (const float*)d_in[11];
    const float* w_coff2 = (const float*)d_in[12];
    const float* b_coff2 = (const float*)d_in[13];
    const float* w_cco   = (const float*)d_in[14];
    const float* b_cco   = (const float*)d_in[15];
    const float* w_cdcn  = (const float*)d_in[16];
    const float* b_cdcn  = (const float*)d_in[17];
    float* outp = (float*)d_out;

    void *pA, *pB, *pCO, *pF;
    cudaGetSymbolAddress(&pA,  g_bufA);
    cudaGetSymbolAddress(&pB,  g_bufB);
    cudaGetSymbolAddress(&pCO, g_co);
    cudaGetSymbolAddress(&pF,  g_feat);
    float* bufA = (float*)pA;
    float* bufB = (float*)pB;
    float* bufCO = (float*)pCO;
    float* feat = (float*)pF;

    const dim3 blk(256);
    const dim3 g64(W_ / 16, H_ / 16, B_);        // 64-out convs & dcn
    const dim3 g216(W_ / 16, H_ / 16, B_ * 3);   // 216-out conv (72 ch / z-slice)

    // ---- first alignment stage ----
    conv3x3_k<128, 64><<<g64, blk>>>(nbr, ref, w_off1, b_off1, bufA, 64, 1);
    conv3x3_k< 64, 64><<<g64, blk>>>(bufA, nullptr, w_off2, b_off2, bufB, 64, 1);
    conv3x3_k< 64, 72><<<g216, blk>>>(bufB, nullptr, w_co, b_co, bufCO, OC_, 0);
    dcn_k<<<g64, blk>>>(nbr, bufCO, w_dcn, b_dcn, feat, 1);

    // ---- cascade stage ----
    conv3x3_k<128, 64><<<g64, blk>>>(feat, ref, w_coff1, b_coff1, bufA, 64, 1);
    conv3x3_k< 64, 64><<<g64, blk>>>(bufA, nullptr, w_coff2, b_coff2, bufB, 64, 1);
    conv3x3_k< 64, 72><<<g216, blk>>>(bufB, nullptr, w_cco, b_cco, bufCO, OC_, 0);
    dcn_k<<<g64, blk>>>(feat, bufCO, w_cdcn, b_cdcn, outp, 1);
}

// round 5
// speedup vs baseline: 1.0962x; 1.0962x over previous
#include <cuda_runtime.h>
#include <cstdint>

// Problem constants (fixed shapes)
#define B_  4
#define H_  160
#define W_  160
#define NF_ 64
#define HW_ (H_ * W_)
#define OC_ 216   // 3 * DG * KK
#define DG_ 8
#define KK_ 9
#define SLOPE_ 0.1f

// ---------------------------------------------------------------------------
// Packed fp32x2 helpers (sm_100+ PTX; 2x FP32 FMA per issue slot)
// ---------------------------------------------------------------------------
__device__ __forceinline__ void fma2(uint64_t& acc, uint64_t a, uint64_t b) {
    asm("fma.rn.f32x2 %0, %1, %2, %0;" : "+l"(acc) : "l"(a), "l"(b));
}
__device__ __forceinline__ uint64_t dup2(float v) {
    uint64_t d;
    uint32_t u = __float_as_uint(v);
    asm("mov.b64 %0, {%1, %1};" : "=l"(d) : "r"(u));
    return d;
}
__device__ __forceinline__ void unpk2(uint64_t v, float& lo, float& hi) {
    uint32_t a, b;
    asm("mov.b64 {%0, %1}, %2;" : "=r"(a), "=r"(b) : "l"(v));
    lo = __uint_as_float(a);
    hi = __uint_as_float(b);
}

// ---------------------------------------------------------------------------
// Scratch buffers (static device globals; no runtime allocation allowed)
// ---------------------------------------------------------------------------
__device__ float g_bufA[B_ * NF_ * HW_];   // 26.2 MB
__device__ float g_bufB[B_ * NF_ * HW_];   // 26.2 MB
__device__ float g_co  [B_ * OC_ * HW_];   // 88.5 MB
__device__ float g_feat[B_ * NF_ * HW_];   // 26.2 MB

// ---------------------------------------------------------------------------
// Direct 3x3 conv, NCHW, stride 1, pad 1 — FFMA2 (f32x2) inner loop.
//  - 16x16 output tile x COUT_BLK channels per block, 256 threads:
//    8x8 pixel-quads (thread owns 2x2 pixels) x 4 channel groups
//    (thread owns NCPT = COUT_BLK/4 channels, packed into NCPT/2 f32x2 accs).
//  - Weight channel-pairs load as single LDS.64; pixel value is lane-dupped.
// ---------------------------------------------------------------------------
template <int CIN, int COUT_BLK>
__global__ __launch_bounds__(256)
void conv3x3_k(const float* __restrict__ in0, const float* __restrict__ in1,
               const float* __restrict__ wgt, const float* __restrict__ bias,
               float* __restrict__ out, int cout_total, int act)
{
    constexpr int CK   = 8;
    constexpr int NCH  = CIN / CK;
    constexpr int NCPT = COUT_BLK / 4;   // 16 or 18 (even)
    constexpr int NP   = NCPT / 2;       // f32x2 pairs per thread

    __shared__ float s_in[CK * 18 * 19];           // [ck][18 rows][19 stride]
    __shared__ float s_w [CK * 9 * COUT_BLK];      // [(ck*9+tap)][cout]

    const int tid = threadIdx.x;
    const int nz  = gridDim.z / B_;
    const int b   = blockIdx.z / nz;
    const int zb  = blockIdx.z - b * nz;
    const int cout_off = zb * COUT_BLK;

    const int cg  = tid >> 6;          // channel group 0..3
    const int t   = tid & 63;
    const int ty2 = (t >> 3) * 2;      // 0..14 step 2
    const int tx2 = (t & 7) * 2;       // 0..14 step 2

    const int by = blockIdx.y * 16;
    const int bx = blockIdx.x * 16;

    uint64_t acc2[2][2][NP];
#pragma unroll
    for (int yy = 0; yy < 2; ++yy)
#pragma unroll
        for (int xx = 0; xx < 2; ++xx)
#pragma unroll
            for (int j = 0; j < NP; ++j) acc2[yy][xx][j] = 0ull;

#pragma unroll 1
    for (int ch = 0; ch < NCH; ++ch) {
        const int cin0 = ch * CK;

        // ---- stage input tile (18x18xCK, zero-padded at borders) ----
#pragma unroll 1
        for (int i = tid; i < CK * 18 * 18; i += 256) {
            const int ck = i / 324;
            const int r  = i - ck * 324;
            const int yy = r / 18;
            const int xx = r - yy * 18;
            const int gy = by + yy - 1;
            const int gx = bx + xx - 1;
            const int c  = cin0 + ck;
            float v = 0.f;
            if (gy >= 0 && gy < H_ && gx >= 0 && gx < W_) {
                if (CIN == 128 && c >= 64)
                    v = in1[(((size_t)b * 64 + (c - 64)) * H_ + gy) * W_ + gx];
                else
                    v = in0[(((size_t)b * 64 + c) * H_ + gy) * W_ + gx];
            }
            s_in[(ck * 18 + yy) * 19 + xx] = v;
        }
        // ---- stage weights ----
#pragma unroll 1
        for (int i = tid; i < CK * 9 * COUT_BLK; i += 256) {
            const int co = i % COUT_BLK;
            const int rt = i / COUT_BLK;          // ck*9 + tap
            const int ck = rt / 9;
            const int tap = rt - ck * 9;
            s_w[i] = wgt[((size_t)(cout_off + co) * CIN + (cin0 + ck)) * 9 + tap];
        }
        __syncthreads();

        // ---- compute (f32x2 packed over output-channel pairs) ----
#pragma unroll 2
        for (int ck = 0; ck < CK; ++ck) {
            float xr[4][4];
#pragma unroll
            for (int yy = 0; yy < 4; ++yy)
#pragma unroll
                for (int xx = 0; xx < 4; ++xx)
                    xr[yy][xx] = s_in[(ck * 18 + ty2 + yy) * 19 + tx2 + xx];

#pragma unroll
            for (int ky = 0; ky < 3; ++ky)
#pragma unroll
                for (int kx = 0; kx < 3; ++kx) {
                    const uint64_t* wrow2 = reinterpret_cast<const uint64_t*>(
                        &s_w[(ck * 9 + ky * 3 + kx) * COUT_BLK + cg * NCPT]);
                    const uint64_t x00 = dup2(xr[ky    ][kx    ]);
                    const uint64_t x01 = dup2(xr[ky    ][kx + 1]);
                    const uint64_t x10 = dup2(xr[ky + 1][kx    ]);
                    const uint64_t x11 = dup2(xr[ky + 1][kx + 1]);
#pragma unroll
                    for (int j = 0; j < NP; ++j) {
                        const uint64_t w2 = wrow2[j];
                        fma2(acc2[0][0][j], x00, w2);
                        fma2(acc2[0][1][j], x01, w2);
                        fma2(acc2[1][0][j], x10, w2);
                        fma2(acc2[1][1][j], x11, w2);
                    }
                }
        }
        __syncthreads();
    }

    // ---- bias + activation + store ----
#pragma unroll
    for (int j = 0; j < NP; ++j) {
        const int co0 = cout_off + cg * NCPT + 2 * j;
        const float bv0 = bias[co0];
        const float bv1 = bias[co0 + 1];
#pragma unroll
        for (int yy = 0; yy < 2; ++yy)
#pragma unroll
            for (int xx = 0; xx < 2; ++xx) {
                float v0, v1;
                unpk2(acc2[yy][xx][j], v0, v1);
                v0 += bv0; v1 += bv1;
                if (act) {
                    v0 = (v0 > 0.f) ? v0 : SLOPE_ * v0;
                    v1 = (v1 > 0.f) ? v1 : SLOPE_ * v1;
                }
                const size_t p = (size_t)(by + ty2 + yy) * W_ + (bx + tx2 + xx);
                out[((size_t)b * cout_total + co0) * HW_ + p]       = v0;
                out[((size_t)b * cout_total + co0 + 1) * HW_ + p]   = v1;
            }
    }
}

// ---------------------------------------------------------------------------
// Modulated deformable conv (DCNv2Pack apply stage) — FFMA2 accumulate.
//  co: [B, 216, H, W] = (144 interleaved (dg,k,{y,x}) offsets, 72 mask logits)
//  Each thread owns one output pixel; 64 outs packed into 32 f32x2 accs.
// ---------------------------------------------------------------------------
__global__ __launch_bounds__(256)
void dcn_k(const float* __restrict__ xin, const float* __restrict__ co,
           const float* __restrict__ wgt, const float* __restrict__ bias,
           float* __restrict__ out, int act)
{
    __shared__ float s_wg[KK_ * 8 * 64];   // 18.4 KB

    const int tid = threadIdx.x;
    const int b   = blockIdx.z;
    const int y   = blockIdx.y * 16 + (tid >> 4);
    const int x   = blockIdx.x * 16 + (tid & 15);

    uint64_t acc2[32];
#pragma unroll
    for (int j = 0; j < 32; ++j) acc2[j] = 0ull;

    const float* cob = co + (size_t)b * OC_ * HW_;
    const int pix = y * W_ + x;

#pragma unroll 1
    for (int g = 0; g < DG_; ++g) {
        __syncthreads();
#pragma unroll 1
        for (int i = tid; i < KK_ * 8 * 64; i += 256) {
            const int o = i & 63;
            const int r = i >> 6;          // k*8 + c
            const int k = r >> 3;
            const int c = r & 7;
            s_wg[i] = wgt[((size_t)o * 64 + g * 8 + c) * KK_ + k];
        }
        __syncthreads();

        const float* xb = xin + ((size_t)b * 64 + g * 8) * HW_;

#pragma unroll 1
        for (int k = 0; k < KK_; ++k) {
            const float offy = cob[(size_t)(g * 18 + 2 * k    ) * HW_ + pix];
            const float offx = cob[(size_t)(g * 18 + 2 * k + 1) * HW_ + pix];
            const float ml   = cob[(size_t)(144 + g * 9 + k   ) * HW_ + pix];
            const float m    = 1.f / (1.f + __expf(-ml));

            const float py = (float)y + (float)(k / 3 - 1) + offy;
            const float px = (float)x + (float)(k % 3 - 1) + offx;
            const float y0f = floorf(py), x0f = floorf(px);
            const float ly = py - y0f,  lx = px - x0f;
            const int y0 = (int)y0f,    x0 = (int)x0f;

            const float w00 = (1.f - ly) * (1.f - lx) * m;
            const float w01 = (1.f - ly) * lx * m;
            const float w10 = ly * (1.f - lx) * m;
            const float w11 = ly * lx * m;

            const bool iy0 = (y0 >= 0)     && (y0 < H_);
            const bool iy1 = (y0 + 1 >= 0) && (y0 + 1 < H_);
            const bool ix0 = (x0 >= 0)     && (x0 < W_);
            const bool ix1 = (x0 + 1 >= 0) && (x0 + 1 < W_);

            const int p00 = y0 * W_ + x0;

#pragma unroll
            for (int c = 0; c < 8; ++c) {
                const float* xc = xb + (size_t)c * HW_;
                float s = 0.f;
                if (iy0 && ix0) s = fmaf(w00, __ldg(xc + p00),          s);
                if (iy0 && ix1) s = fmaf(w01, __ldg(xc + p00 + 1),      s);
                if (iy1 && ix0) s = fmaf(w10, __ldg(xc + p00 + W_),     s);
                if (iy1 && ix1) s = fmaf(w11, __ldg(xc + p00 + W_ + 1), s);

                const uint64_t s2 = dup2(s);
                const ulonglong2* wr =
                    reinterpret_cast<const ulonglong2*>(&s_wg[(k * 8 + c) * 64]);
#pragma unroll
                for (int q = 0; q < 16; ++q) {
                    const ulonglong2 w4 = wr[q];   // 2 channel-pairs
                    fma2(acc2[2 * q    ], s2, w4.x);
                    fma2(acc2[2 * q + 1], s2, w4.y);
                }
            }
        }
    }

#pragma unroll
    for (int j = 0; j < 32; ++j) {
        float v0, v1;
        unpk2(acc2[j], v0, v1);
        v0 += bias[2 * j];
        v1 += bias[2 * j + 1];
        if (act) {
            v0 = (v0 > 0.f) ? v0 : SLOPE_ * v0;
            v1 = (v1 > 0.f) ? v1 : SLOPE_ * v1;
        }
        out[(((size_t)b * 64 + 2 * j    ) * H_ + y) * W_ + x] = v0;
        out[(((size_t)b * 64 + 2 * j + 1) * H_ + y) * W_ + x] = v1;
    }
}

// ---------------------------------------------------------------------------
// Launch
// ---------------------------------------------------------------------------
extern "C" void kernel_launch(void* const* d_in, const int* in_sizes, int n_in,
                              void* d_out, int out_size)
{
    const float* nbr     = (const float*)d_in[0];
    const float* ref     = (const float*)d_in[1];
    const float* w_off1  = (const float*)d_in[2];
    const float* b_off1  = (const float*)d_in[3];
    const float* w_off2  = (const float*)d_in[4];
    const float* b_off2  = (const float*)d_in[5];
    const float* w_co    = (const float*)d_in[6];
    const float* b_co    = (const float*)d_in[7];
    const float* w_dcn   = (const float*)d_in[8];
    const float* b_dcn   = (const float*)d_in[9];
    const float* w_coff1 = (const float*)d_in[10];
    const float* b_coff1 = (const float*)d_in[11];
    const float* w_coff2 = (const float*)d_in[12];
    const float* b_coff2 = (const float*)d_in[13];
    const float* w_cco   = (const float*)d_in[14];
    const float* b_cco   = (const float*)d_in[15];
    const float* w_cdcn  = (const float*)d_in[16];
    const float* b_cdcn  = (const float*)d_in[17];
    float* outp = (float*)d_out;

    void *pA, *pB, *pCO, *pF;
    cudaGetSymbolAddress(&pA,  g_bufA);
    cudaGetSymbolAddress(&pB,  g_bufB);
    cudaGetSymbolAddress(&pCO, g_co);
    cudaGetSymbolAddress(&pF,  g_feat);
    float* bufA = (float*)pA;
    float* bufB = (float*)pB;
    float* bufCO = (float*)pCO;
    float* feat = (float*)pF;

    const dim3 blk(256);
    const dim3 g64(W_ / 16, H_ / 16, B_);        // 64-out convs & dcn
    const dim3 g216(W_ / 16, H_ / 16, B_ * 3);   // 216-out conv (72 ch / z-slice)

    // ---- first alignment stage ----
    conv3x3_k<128, 64><<<g64, blk>>>(nbr, ref, w_off1, b_off1, bufA, 64, 1);
    conv3x3_k< 64, 64><<<g64, blk>>>(bufA, nullptr, w_off2, b_off2, bufB, 64, 1);
    conv3x3_k< 64, 72><<<g216, blk>>>(bufB, nullptr, w_co, b_co, bufCO, OC_, 0);
    dcn_k<<<g64, blk>>>(nbr, bufCO, w_dcn, b_dcn, feat, 1);

    // ---- cascade stage ----
    conv3x3_k<128, 64><<<g64, blk>>>(feat, ref, w_coff1, b_coff1, bufA, 64, 1);
    conv3x3_k< 64, 64><<<g64, blk>>>(bufA, nullptr, w_coff2, b_coff2, bufB, 64, 1);
    conv3x3_k< 64, 72><<<g216, blk>>>(bufB, nullptr, w_cco, b_cco, bufCO, OC_, 0);
    dcn_k<<<g64, blk>>>(feat, bufCO, w_cdcn, b_cdcn, outp, 1);
}

// round 6
// speedup vs baseline: 1.1702x; 1.0675x over previous
#include <cuda_runtime.h>
#include <cstdint>

// Problem constants (fixed shapes)
#define B_  4
#define H_  160
#define W_  160
#define NF_ 64
#define HW_ (H_ * W_)
#define OC_ 216   // 3 * DG * KK
#define DG_ 8
#define KK_ 9
#define SLOPE_ 0.1f

// ---------------------------------------------------------------------------
// Packed fp32x2 helpers (sm_100+ PTX; 2x FP32 FMA per issue slot)
// ---------------------------------------------------------------------------
__device__ __forceinline__ void fma2(uint64_t& acc, uint64_t a, uint64_t b) {
    asm("fma.rn.f32x2 %0, %1, %2, %0;" : "+l"(acc) : "l"(a), "l"(b));
}
__device__ __forceinline__ uint64_t dup2(float v) {
    uint64_t d;
    uint32_t u = __float_as_uint(v);
    asm("mov.b64 %0, {%1, %1};" : "=l"(d) : "r"(u));
    return d;
}
__device__ __forceinline__ void unpk2(uint64_t v, float& lo, float& hi) {
    uint32_t a, b;
    asm("mov.b64 {%0, %1}, %2;" : "=r"(a), "=r"(b) : "l"(v));
    lo = __uint_as_float(a);
    hi = __uint_as_float(b);
}

// cp.async 4B with zero-fill predicate (src-size 0 -> writes zeros)
__device__ __forceinline__ void cp4(uint32_t saddr, const void* gaddr, bool ok) {
    asm volatile("cp.async.ca.shared.global [%0], [%1], 4, %2;"
                 :: "r"(saddr), "l"(gaddr), "r"(ok ? 4 : 0));
}
#define CP_COMMIT() asm volatile("cp.async.commit_group;")
#define CP_WAIT1()  asm volatile("cp.async.wait_group 1;" ::: "memory")

// ---------------------------------------------------------------------------
// Scratch buffers (static device globals; no runtime allocation allowed)
// ---------------------------------------------------------------------------
__device__ float g_bufA [B_ * NF_ * HW_];   // 26.2 MB
__device__ float g_bufB [B_ * NF_ * HW_];   // 26.2 MB
__device__ float g_co   [B_ * OC_ * HW_];   // 88.5 MB
__device__ float g_feat [B_ * NF_ * HW_];   // 26.2 MB (NCHW)
__device__ float g_nbrT [B_ * HW_ * NF_];   // 26.2 MB (NHWC)
__device__ float g_featT[B_ * HW_ * NF_];   // 26.2 MB (NHWC)

// ---------------------------------------------------------------------------
// NCHW -> NHWC transpose (tiled via smem). grid (HW/64, B), 256 threads.
// ---------------------------------------------------------------------------
__global__ __launch_bounds__(256)
void t_k(const float* __restrict__ in, float* __restrict__ out)
{
    __shared__ float s[64][65];
    const int tid = threadIdx.x;
    const int b = blockIdx.y;
    const int p0 = blockIdx.x * 64;
#pragma unroll 1
    for (int i = tid; i < 64 * 64; i += 256) {
        const int c = i >> 6, p = i & 63;
        s[c][p] = in[((size_t)b * 64 + c) * HW_ + p0 + p];
    }
    __syncthreads();
#pragma unroll 1
    for (int i = tid; i < 64 * 64; i += 256) {
        const int p = i >> 6, c = i & 63;
        out[((size_t)b * HW_ + p0 + p) * 64 + c] = s[c][p];
    }
}

// ---------------------------------------------------------------------------
// Direct 3x3 conv, NCHW, stride 1, pad 1 — FFMA2 inner loop,
// cp.async double-buffered staging pipeline (input tile + weights).
// Dynamic smem layout: [ s_in x2 | s_w x2 ].
// ---------------------------------------------------------------------------
template <int CIN, int COUT_BLK>
__global__ __launch_bounds__(256, 2)
void conv3x3_k(const float* __restrict__ in0, const float* __restrict__ in1,
               const float* __restrict__ wgt, const float* __restrict__ bias,
               float* __restrict__ out, int cout_total, int act)
{
    constexpr int CK   = 8;
    constexpr int NCH  = CIN / CK;
    constexpr int NCPT = COUT_BLK / 4;   // 16 or 18 (even)
    constexpr int NP   = NCPT / 2;       // f32x2 pairs per thread
    constexpr int INB  = CK * 18 * 20;   // floats per input buffer (stride 20)
    constexpr int WB   = CK * 9 * COUT_BLK;

    extern __shared__ float sm[];
    float* s_in0 = sm;
    float* s_w0  = sm + 2 * INB;
    const uint32_t s_u32 = (uint32_t)__cvta_generic_to_shared(sm);

    const int tid = threadIdx.x;
    const int nz  = gridDim.z / B_;
    const int b   = blockIdx.z / nz;
    const int zb  = blockIdx.z - b * nz;
    const int cout_off = zb * COUT_BLK;

    const int cg  = tid >> 6;          // channel group 0..3
    const int t   = tid & 63;
    const int ty2 = (t >> 3) * 2;      // 0..14 step 2
    const int tx2 = (t & 7) * 2;       // 0..14 step 2

    const int by = blockIdx.y * 16;
    const int bx = blockIdx.x * 16;

    uint64_t acc2[2][2][NP];
#pragma unroll
    for (int yy = 0; yy < 2; ++yy)
#pragma unroll
        for (int xx = 0; xx < 2; ++xx)
#pragma unroll
            for (int j = 0; j < NP; ++j) acc2[yy][xx][j] = 0ull;

    // ---- staging (cp.async) ----
    auto stage = [&](int ch, int pb) {
        const int cin0 = ch * CK;
        const uint32_t in_b = s_u32 + (uint32_t)(pb * INB) * 4u;
        const uint32_t w_b  = s_u32 + (uint32_t)(2 * INB + pb * WB) * 4u;
#pragma unroll 1
        for (int i = tid; i < CK * 18 * 18; i += 256) {
            const int ck = i / 324;
            const int r  = i - ck * 324;
            const int yy = r / 18;
            const int xx = r - yy * 18;
            const int gy = by + yy - 1;
            const int gx = bx + xx - 1;
            const int c  = cin0 + ck;
            const bool ok = (gy >= 0 && gy < H_ && gx >= 0 && gx < W_);
            const int cy = ok ? gy : 0;
            const int cx = ok ? gx : 0;
            const float* src;
            if (CIN == 128 && c >= 64)
                src = in1 + (((size_t)b * 64 + (c - 64)) * H_ + cy) * W_ + cx;
            else
                src = in0 + (((size_t)b * 64 + c) * H_ + cy) * W_ + cx;
            cp4(in_b + (uint32_t)((ck * 18 + yy) * 20 + xx) * 4u, src, ok);
        }
#pragma unroll 1
        for (int i = tid; i < WB; i += 256) {
            const int co = i % COUT_BLK;
            const int rt = i / COUT_BLK;          // ck*9 + tap
            const int ck = rt / 9;
            const int tap = rt - ck * 9;
            cp4(w_b + (uint32_t)i * 4u,
                wgt + ((size_t)(cout_off + co) * CIN + (cin0 + ck)) * 9 + tap,
                true);
        }
    };

    stage(0, 0);
    CP_COMMIT();

#pragma unroll 1
    for (int ch = 0; ch < NCH; ++ch) {
        const int buf = ch & 1;
        if (ch + 1 < NCH) stage(ch + 1, buf ^ 1);
        CP_COMMIT();
        CP_WAIT1();
        __syncthreads();

        const float* si = s_in0 + buf * INB;
        const float* sw = s_w0 + buf * WB;

#pragma unroll 2
        for (int ck = 0; ck < CK; ++ck) {
            float xr[4][4];
#pragma unroll
            for (int yy = 0; yy < 4; ++yy) {
                const float2* row = reinterpret_cast<const float2*>(
                    si + (ck * 18 + ty2 + yy) * 20 + tx2);
                const float2 p01 = row[0];
                const float2 p23 = row[1];
                xr[yy][0] = p01.x; xr[yy][1] = p01.y;
                xr[yy][2] = p23.x; xr[yy][3] = p23.y;
            }

#pragma unroll
            for (int ky = 0; ky < 3; ++ky)
#pragma unroll
                for (int kx = 0; kx < 3; ++kx) {
                    const uint64_t* wrow2 = reinterpret_cast<const uint64_t*>(
                        sw + (ck * 9 + ky * 3 + kx) * COUT_BLK + cg * NCPT);
                    const uint64_t x00 = dup2(xr[ky    ][kx    ]);
                    const uint64_t x01 = dup2(xr[ky    ][kx + 1]);
                    const uint64_t x10 = dup2(xr[ky + 1][kx    ]);
                    const uint64_t x11 = dup2(xr[ky + 1][kx + 1]);
#pragma unroll
                    for (int j = 0; j < NP; ++j) {
                        const uint64_t w2 = wrow2[j];
                        fma2(acc2[0][0][j], x00, w2);
                        fma2(acc2[0][1][j], x01, w2);
                        fma2(acc2[1][0][j], x10, w2);
                        fma2(acc2[1][1][j], x11, w2);
                    }
                }
        }
        __syncthreads();
    }

    // ---- bias + activation + store ----
#pragma unroll
    for (int j = 0; j < NP; ++j) {
        const int co0 = cout_off + cg * NCPT + 2 * j;
        const float bv0 = bias[co0];
        const float bv1 = bias[co0 + 1];
#pragma unroll
        for (int yy = 0; yy < 2; ++yy)
#pragma unroll
            for (int xx = 0; xx < 2; ++xx) {
                float v0, v1;
                unpk2(acc2[yy][xx][j], v0, v1);
                v0 += bv0; v1 += bv1;
                if (act) {
                    v0 = (v0 > 0.f) ? v0 : SLOPE_ * v0;
                    v1 = (v1 > 0.f) ? v1 : SLOPE_ * v1;
                }
                const size_t p = (size_t)(by + ty2 + yy) * W_ + (bx + tx2 + xx);
                out[((size_t)b * cout_total + co0) * HW_ + p]     = v0;
                out[((size_t)b * cout_total + co0 + 1) * HW_ + p] = v1;
            }
    }
}

// ---------------------------------------------------------------------------
// Modulated deformable conv (DCNv2Pack apply) — NHWC gathers + FFMA2.
//  xT:  [B, H, W, 64] NHWC input features
//  co:  [B, 216, H, W] offsets (g*18+2k+{y,x}) + mask logits (144+g*9+k)
//  out: NCHW output; outT: optional NHWC copy (for the cascade dcn input).
// ---------------------------------------------------------------------------
__global__ __launch_bounds__(256, 2)
void dcn_k(const float* __restrict__ xT, const float* __restrict__ co,
           const float* __restrict__ wgt, const float* __restrict__ bias,
           float* __restrict__ out, float* __restrict__ outT, int act)
{
    __shared__ float s_wg[KK_ * 8 * 64];   // 18.4 KB

    const int tid = threadIdx.x;
    const int b   = blockIdx.z;
    const int y   = blockIdx.y * 16 + (tid >> 4);
    const int x   = blockIdx.x * 16 + (tid & 15);

    uint64_t acc2[32];
#pragma unroll
    for (int j = 0; j < 32; ++j) acc2[j] = 0ull;

    const float* cob = co + (size_t)b * OC_ * HW_;
    const float* xb  = xT + (size_t)b * HW_ * 64;
    const int pix = y * W_ + x;

#pragma unroll 1
    for (int g = 0; g < DG_; ++g) {
        __syncthreads();
#pragma unroll 1
        for (int i = tid; i < KK_ * 8 * 64; i += 256) {
            const int o = i & 63;
            const int r = i >> 6;          // k*8 + c
            const int k = r >> 3;
            const int c = r & 7;
            s_wg[i] = wgt[((size_t)o * 64 + g * 8 + c) * KK_ + k];
        }
        __syncthreads();

#pragma unroll 1
        for (int k = 0; k < KK_; ++k) {
            const float offy = cob[(size_t)(g * 18 + 2 * k    ) * HW_ + pix];
            const float offx = cob[(size_t)(g * 18 + 2 * k + 1) * HW_ + pix];
            const float ml   = cob[(size_t)(144 + g * 9 + k   ) * HW_ + pix];
            const float m    = 1.f / (1.f + __expf(-ml));

            const float py = (float)y + (float)(k / 3 - 1) + offy;
            const float px = (float)x + (float)(k % 3 - 1) + offx;
            const float y0f = floorf(py), x0f = floorf(px);
            const float ly = py - y0f,  lx = px - x0f;
            const int y0 = (int)y0f,    x0 = (int)x0f;

            const float w00 = (1.f - ly) * (1.f - lx) * m;
            const float w01 = (1.f - ly) * lx * m;
            const float w10 = ly * (1.f - lx) * m;
            const float w11 = ly * lx * m;

            const bool iy0 = (y0 >= 0)     && (y0 < H_);
            const bool iy1 = (y0 + 1 >= 0) && (y0 + 1 < H_);
            const bool ix0 = (x0 >= 0)     && (x0 < W_);
            const bool ix1 = (x0 + 1 >= 0) && (x0 + 1 < W_);

            // gather 4 corners x 8 channels (two float4 each, NHWC)
            float4 c00a = {0,0,0,0}, c00b = {0,0,0,0};
            float4 c01a = {0,0,0,0}, c01b = {0,0,0,0};
            float4 c10a = {0,0,0,0}, c10b = {0,0,0,0};
            float4 c11a = {0,0,0,0}, c11b = {0,0,0,0};
            if (iy0 && ix0) {
                const float4* p = (const float4*)(xb + ((size_t)(y0 * W_ + x0)) * 64 + g * 8);
                c00a = __ldg(p); c00b = __ldg(p + 1);
            }
            if (iy0 && ix1) {
                const float4* p = (const float4*)(xb + ((size_t)(y0 * W_ + x0 + 1)) * 64 + g * 8);
                c01a = __ldg(p); c01b = __ldg(p + 1);
            }
            if (iy1 && ix0) {
                const float4* p = (const float4*)(xb + ((size_t)((y0 + 1) * W_ + x0)) * 64 + g * 8);
                c10a = __ldg(p); c10b = __ldg(p + 1);
            }
            if (iy1 && ix1) {
                const float4* p = (const float4*)(xb + ((size_t)((y0 + 1) * W_ + x0 + 1)) * 64 + g * 8);
                c11a = __ldg(p); c11b = __ldg(p + 1);
            }

            // bilinear blend, 8 channels
            float s[8];
            s[0] = w00*c00a.x + w01*c01a.x + w10*c10a.x + w11*c11a.x;
            s[1] = w00*c00a.y + w01*c01a.y + w10*c10a.y + w11*c11a.y;
            s[2] = w00*c00a.z + w01*c01a.z + w10*c10a.z + w11*c11a.z;
            s[3] = w00*c00a.w + w01*c01a.w + w10*c10a.w + w11*c11a.w;
            s[4] = w00*c00b.x + w01*c01b.x + w10*c10b.x + w11*c11b.x;
            s[5] = w00*c00b.y + w01*c01b.y + w10*c10b.y + w11*c11b.y;
            s[6] = w00*c00b.z + w01*c01b.z + w10*c10b.z + w11*c11b.z;
            s[7] = w00*c00b.w + w01*c01b.w + w10*c10b.w + w11*c11b.w;

#pragma unroll
            for (int c = 0; c < 8; ++c) {
                const uint64_t s2 = dup2(s[c]);
                const ulonglong2* wr =
                    reinterpret_cast<const ulonglong2*>(&s_wg[(k * 8 + c) * 64]);
#pragma unroll
                for (int q = 0; q < 16; ++q) {
                    const ulonglong2 w4 = wr[q];   // 2 channel-pairs
                    fma2(acc2[2 * q    ], s2, w4.x);
                    fma2(acc2[2 * q + 1], s2, w4.y);
                }
            }
        }
    }

    float v[64];
#pragma unroll
    for (int j = 0; j < 32; ++j) {
        float v0, v1;
        unpk2(acc2[j], v0, v1);
        v0 += bias[2 * j];
        v1 += bias[2 * j + 1];
        if (act) {
            v0 = (v0 > 0.f) ? v0 : SLOPE_ * v0;
            v1 = (v1 > 0.f) ? v1 : SLOPE_ * v1;
        }
        v[2 * j] = v0; v[2 * j + 1] = v1;
    }
#pragma unroll
    for (int o = 0; o < 64; ++o)
        out[(((size_t)b * 64 + o) * H_ + y) * W_ + x] = v[o];
    if (outT) {
        float4* dst = (float4*)(outT + ((size_t)b * HW_ + pix) * 64);
#pragma unroll
        for (int q = 0; q < 16; ++q)
            dst[q] = make_float4(v[4*q], v[4*q+1], v[4*q+2], v[4*q+3]);
    }
}

// ---------------------------------------------------------------------------
// Launch
// ---------------------------------------------------------------------------
extern "C" void kernel_launch(void* const* d_in, const int* in_sizes, int n_in,
                              void* d_out, int out_size)
{
    const float* nbr     = (const float*)d_in[0];
    const float* ref     = (const float*)d_in[1];
    const float* w_off1  = (const float*)d_in[2];
    const float* b_off1  = (const float*)d_in[3];
    const float* w_off2  = (const float*)d_in[4];
    const float* b_off2  = (const float*)d_in[5];
    const float* w_co    = (const float*)d_in[6];
    const float* b_co    = (const float*)d_in[7];
    const float* w_dcn   = (const float*)d_in[8];
    const float* b_dcn   = (const float*)d_in[9];
    const float* w_coff1 = (const float*)d_in[10];
    const float* b_coff1 = (const float*)d_in[11];
    const float* w_coff2 = (const float*)d_in[12];
    const float* b_coff2 = (const float*)d_in[13];
    const float* w_cco   = (const float*)d_in[14];
    const float* b_cco   = (const float*)d_in[15];
    const float* w_cdcn  = (const float*)d_in[16];
    const float* b_cdcn  = (const float*)d_in[17];
    float* outp = (float*)d_out;

    void *pA, *pB, *pCO, *pF, *pNT, *pFT;
    cudaGetSymbolAddress(&pA,  g_bufA);
    cudaGetSymbolAddress(&pB,  g_bufB);
    cudaGetSymbolAddress(&pCO, g_co);
    cudaGetSymbolAddress(&pF,  g_feat);
    cudaGetSymbolAddress(&pNT, g_nbrT);
    cudaGetSymbolAddress(&pFT, g_featT);
    float* bufA  = (float*)pA;
    float* bufB  = (float*)pB;
    float* bufCO = (float*)pCO;
    float* feat  = (float*)pF;
    float* nbrT  = (float*)pNT;
    float* featT = (float*)pFT;

    // dynamic smem sizes for the pipelined conv
    constexpr int SM64 = (2 * 8 * 18 * 20 + 2 * 8 * 9 * 64) * 4;   // 59904
    constexpr int SM72 = (2 * 8 * 18 * 20 + 2 * 8 * 9 * 72) * 4;   // 64512
    cudaFuncSetAttribute(conv3x3_k<128, 64>,
                         cudaFuncAttributeMaxDynamicSharedMemorySize, SM64);
    cudaFuncSetAttribute(conv3x3_k<64, 64>,
                         cudaFuncAttributeMaxDynamicSharedMemorySize, SM64);
    cudaFuncSetAttribute(conv3x3_k<64, 72>,
                         cudaFuncAttributeMaxDynamicSharedMemorySize, SM72);

    const dim3 blk(256);
    const dim3 g64(W_ / 16, H_ / 16, B_);        // 64-out convs & dcn
    const dim3 g216(W_ / 16, H_ / 16, B_ * 3);   // 216-out conv
    const dim3 gT(HW_ / 64, B_);

    // ---- transpose nbr to NHWC for dcn gathers ----
    t_k<<<gT, blk>>>(nbr, nbrT);

    // ---- first alignment stage ----
    conv3x3_k<128, 64><<<g64, blk, SM64>>>(nbr, ref, w_off1, b_off1, bufA, 64, 1);
    conv3x3_k< 64, 64><<<g64, blk, SM64>>>(bufA, nullptr, w_off2, b_off2, bufB, 64, 1);
    conv3x3_k< 64, 72><<<g216, blk, SM72>>>(bufB, nullptr, w_co, b_co, bufCO, OC_, 0);
    dcn_k<<<g64, blk>>>(nbrT, bufCO, w_dcn, b_dcn, feat, featT, 1);

    // ---- cascade stage ----
    conv3x3_k<128, 64><<<g64, blk, SM64>>>(feat, ref, w_coff1, b_coff1, bufA, 64, 1);
    conv3x3_k< 64, 64><<<g64, blk, SM64>>>(bufA, nullptr, w_coff2, b_coff2, bufB, 64, 1);
    conv3x3_k< 64, 72><<<g216, blk, SM72>>>(bufB, nullptr, w_cco, b_cco, bufCO, OC_, 0);
    dcn_k<<<g64, blk>>>(featT, bufCO, w_cdcn, b_cdcn, outp, nullptr, 1);
}

// round 11
// speedup vs baseline: 1.6256x; 1.3891x over previous
#include <cuda_runtime.h>
#include <cuda_bf16.h>
#include <mma.h>
#include <cstdint>

using namespace nvcuda;

// Problem constants (fixed shapes)
#define B_  4
#define H_  160
#define W_  160
#define HW_ (H_ * W_)
#define OC_ 216   // 3 * DG * KK
#define DG_ 8
#define KK_ 9
#define SLOPE_ 0.1f

// ---------------------------------------------------------------------------
// Helpers
// ---------------------------------------------------------------------------
__device__ __forceinline__ void fma2(uint64_t& acc, uint64_t a, uint64_t b) {
    asm("fma.rn.f32x2 %0, %1, %2, %0;" : "+l"(acc) : "l"(a), "l"(b));
}
__device__ __forceinline__ uint64_t dup2(float v) {
    uint64_t d; uint32_t u = __float_as_uint(v);
    asm("mov.b64 %0, {%1, %1};" : "=l"(d) : "r"(u));
    return d;
}
__device__ __forceinline__ void unpk2(uint64_t v, float& lo, float& hi) {
    uint32_t a, b;
    asm("mov.b64 {%0, %1}, %2;" : "=r"(a), "=r"(b) : "l"(v));
    lo = __uint_as_float(a); hi = __uint_as_float(b);
}
__device__ __forceinline__ void cp16(uint32_t s, const void* g) {
    asm volatile("cp.async.cg.shared.global [%0], [%1], 16;" :: "r"(s), "l"(g));
}
#define CP_COMMIT() asm volatile("cp.async.commit_group;")
#define CP_WAIT0()  asm volatile("cp.async.wait_group 0;" ::: "memory")

// ---------------------------------------------------------------------------
// Scratch buffers (static device globals; no runtime allocation allowed)
// ---------------------------------------------------------------------------
__device__ float g_bufA [B_ * HW_ * 64];   // NHWC activations
__device__ float g_bufB [B_ * HW_ * 64];   // NHWC activations
__device__ float g_co   [B_ * OC_ * HW_];  // NCHW offsets/masks
__device__ float g_nbrT [B_ * HW_ * 64];   // NHWC
__device__ float g_refT [B_ * HW_ * 64];   // NHWC
__device__ float g_featT[B_ * HW_ * 64];   // NHWC

// packed bf16 hi/lo weight blobs: [slice][half][tap][{hi,lo}][k=64][NPs]
__device__ __nv_bfloat16 g_wb1[2 * 9 * 2 * 64 * 72];       // conv1 (2 halves)
__device__ __nv_bfloat16 g_wb2[9 * 2 * 64 * 72];           // conv2
__device__ __nv_bfloat16 g_wb3[3 * 9 * 2 * 64 * 88];       // co (3 slices, NP=80)
__device__ __nv_bfloat16 g_wb4[2 * 9 * 2 * 64 * 72];
__device__ __nv_bfloat16 g_wb5[9 * 2 * 64 * 72];
__device__ __nv_bfloat16 g_wb6[3 * 9 * 2 * 64 * 88];

// ---------------------------------------------------------------------------
// NCHW -> NHWC transpose
// ---------------------------------------------------------------------------
__global__ __launch_bounds__(256)
void t_k(const float* __restrict__ in, float* __restrict__ out)
{
    __shared__ float s[64][65];
    const int tid = threadIdx.x;
    const int b = blockIdx.y;
    const int p0 = blockIdx.x * 64;
#pragma unroll 1
    for (int i = tid; i < 64 * 64; i += 256) {
        const int c = i >> 6, p = i & 63;
        s[c][p] = in[((size_t)b * 64 + c) * HW_ + p0 + p];
    }
    __syncthreads();
#pragma unroll 1
    for (int i = tid; i < 64 * 64; i += 256) {
        const int p = i >> 6, c = i & 63;
        out[((size_t)b * HW_ + p0 + p) * 64 + c] = s[c][p];
    }
}

// ---------------------------------------------------------------------------
// Weight packing: w[cout][cin][3][3] fp32 -> [slice][half][tap][{hi,lo}][k][NPs]
// bf16, hi/lo split. n in [nout, np) zero-filled; cols [np, nps) unused.
// ---------------------------------------------------------------------------
__global__ __launch_bounds__(256)
void pack_k(const float* __restrict__ w, int cin_total, int nout, int np,
            int nps, int halves, __nv_bfloat16* __restrict__ blob)
{
    const int slice = blockIdx.y;
    const int cout0 = slice * nout;
    const int taphalf = 64 * nps;
    const int tapsz = 2 * taphalf;
    const int slice_stride = halves * 9 * tapsz;
    const int total = halves * 9 * 64 * np;
#pragma unroll 1
    for (int i = blockIdx.x * 256 + threadIdx.x; i < total; i += gridDim.x * 256) {
        const int n = i % np;
        const int k = (i / np) & 63;
        const int t = (i / (np * 64)) % 9;
        const int h = i / (np * 64 * 9);
        float x = 0.f;
        if (n < nout)
            x = w[((size_t)(cout0 + n) * cin_total + h * 64 + k) * 9 + t];
        const __nv_bfloat16 hi = __float2bfloat16(x);
        const __nv_bfloat16 lo = __float2bfloat16(x - __bfloat162float(hi));
        __nv_bfloat16* dst = blob + (size_t)slice * slice_stride
                             + (h * 9 + t) * tapsz + k * nps + n;
        dst[0] = hi;
        dst[taphalf] = lo;
    }
}

// ---------------------------------------------------------------------------
// wmma bf16 conv3x3 (implicit GEMM, hi/lo 3-pass split).
//  Block: 128 px (8 rows x 16 cols), 8 warps; warp w owns px row w (M-tile 16).
//  N = NP (64 or 80 padded from 72), NT = NP/16 n-tiles.
//  K = HALVES * 9 taps * 64 ch; A staged in smem bf16 hi/lo (halo 10x18, ld 72),
//  B streamed per tap via cp.async from packed blob (ld NPs = NP+8).
//  NOUT==64 -> NHWC fp32 out; NOUT==72 -> NCHW out (3 slices via blockIdx.z).
// ---------------------------------------------------------------------------
template <int NOUT, int NP, int HALVES>
__global__ __launch_bounds__(256, 2)
void tconv_k(const float* __restrict__ in0, const float* __restrict__ in1,
             const __nv_bfloat16* __restrict__ blob,
             const float* __restrict__ bias, float* __restrict__ out, int act)
{
    constexpr int NPs     = NP + 8;
    constexpr int NT      = NP / 16;
    constexpr int TAPHALF = 64 * NPs;            // elements (hi or lo) per tap
    constexpr int TAPSZ   = 2 * TAPHALF;
    constexpr int B_BYTES = TAPSZ * 2;
    constexpr int A_OFF   = B_BYTES;             // bytes
    constexpr int A_BYTES = 180 * 72 * 2;        // one bf16 tile (10x18 px, ld 72)
    constexpr int NSLICE  = (NOUT == 72) ? 3 : 1;
    constexpr int LDO     = NP + 4;

    extern __shared__ uint8_t sm[];
    __nv_bfloat16* smB  = (__nv_bfloat16*)sm;
    __nv_bfloat16* aHiB = (__nv_bfloat16*)(sm + A_OFF);
    __nv_bfloat16* aLoB = (__nv_bfloat16*)(sm + A_OFF + A_BYTES);
    uint32_t* aHi32 = (uint32_t*)aHiB;
    uint32_t* aLo32 = (uint32_t*)aLoB;
    const uint32_t smb = (uint32_t)__cvta_generic_to_shared(sm);

    const int tid  = threadIdx.x;
    const int w    = tid >> 5;
    const int slice = blockIdx.z % NSLICE;
    const int b     = blockIdx.z / NSLICE;
    const int by = blockIdx.y * 8;
    const int bx = blockIdx.x * 16;

    wmma::fragment<wmma::accumulator, 16, 16, 16, float> acc[NT];
#pragma unroll
    for (int nt = 0; nt < NT; ++nt) wmma::fill_fragment(acc[nt], 0.0f);

    const __nv_bfloat16* bl = blob + (size_t)slice * (HALVES * 9 * TAPSZ);

#pragma unroll 1
    for (int h = 0; h < HALVES; ++h) {
        __syncthreads();   // previous half's compute fully done before A restage

        // ---- stage A: NHWC fp32 -> bf16 hi/lo (halo 10x18, ld 72) ----
        const float* src = ((HALVES == 2 && h == 1) ? in1 : in0) + (size_t)b * HW_ * 64;
#pragma unroll 1
        for (int i = tid; i < 180 * 32; i += 256) {
            const int pix = i >> 5;        // pr*18 + pc
            const int j   = i & 31;        // channel pair
            const int pr  = pix / 18, pc = pix - pr * 18;
            const int gy = by + pr - 1, gx = bx + pc - 1;
            float2 v = make_float2(0.f, 0.f);
            if (gy >= 0 && gy < H_ && gx >= 0 && gx < W_)
                v = *(const float2*)(src + ((size_t)(gy * W_ + gx)) * 64 + 2 * j);
            const __nv_bfloat16 h0 = __float2bfloat16(v.x);
            const __nv_bfloat16 h1 = __float2bfloat16(v.y);
            const __nv_bfloat16 l0 = __float2bfloat16(v.x - __bfloat162float(h0));
            const __nv_bfloat16 l1 = __float2bfloat16(v.y - __bfloat162float(h1));
            aHi32[pix * 36 + j] = (uint32_t)__bfloat16_as_ushort(h0) |
                                  ((uint32_t)__bfloat16_as_ushort(h1) << 16);
            aLo32[pix * 36 + j] = (uint32_t)__bfloat16_as_ushort(l0) |
                                  ((uint32_t)__bfloat16_as_ushort(l1) << 16);
        }

#pragma unroll 1
        for (int t = 0; t < 9; ++t) {
            __syncthreads();   // prev tap compute done (B free); A visible at t=0
            // ---- stream B tap (hi+lo) ----
            const __nv_bfloat16* bsrc = bl + (size_t)(h * 9 + t) * TAPSZ;
#pragma unroll 1
            for (int i = tid * 16; i < B_BYTES; i += 256 * 16)
                cp16(smb + i, (const uint8_t*)bsrc + i);
            CP_COMMIT();
            CP_WAIT0();
            __syncthreads();

            const int ky = t / 3, kx = t - ky * 3;
            const int abase0 = ((w + ky) * 18 + kx) * 72;
#pragma unroll
            for (int kc = 0; kc < 4; ++kc) {
                wmma::fragment<wmma::matrix_a, 16, 16, 16, __nv_bfloat16,
                               wmma::row_major> fa_h, fa_l;
                wmma::load_matrix_sync(fa_h, aHiB + abase0 + kc * 16, 72);
                wmma::load_matrix_sync(fa_l, aLoB + abase0 + kc * 16, 72);
#pragma unroll
                for (int nt = 0; nt < NT; ++nt) {
                    wmma::fragment<wmma::matrix_b, 16, 16, 16, __nv_bfloat16,
                                   wmma::row_major> fb;
                    wmma::load_matrix_sync(fb, smB + kc * 16 * NPs + nt * 16, NPs);
                    wmma::mma_sync(acc[nt], fa_h, fb, acc[nt]);
                    wmma::mma_sync(acc[nt], fa_l, fb, acc[nt]);
                    wmma::load_matrix_sync(fb, smB + TAPHALF + kc * 16 * NPs + nt * 16, NPs);
                    wmma::mma_sync(acc[nt], fa_h, fb, acc[nt]);
                }
            }
        }
    }

    // ---- epilogue ----
    __syncthreads();
    float* smf = (float*)(sm + A_OFF);   // reuse A region
#pragma unroll
    for (int nt = 0; nt < NT; ++nt)
        wmma::store_matrix_sync(smf + w * 16 * LDO + nt * 16, acc[nt], LDO,
                                wmma::mem_row_major);
    __syncthreads();

    if (NOUT == 64) {
#pragma unroll 1
        for (int i = tid; i < 128 * 16; i += 256) {
            const int c4 = i & 15;
            const int p  = i >> 4;
            float4 v = *(float4*)(smf + p * LDO + 4 * c4);
            v.x += bias[4 * c4];
            v.y += bias[4 * c4 + 1];
            v.z += bias[4 * c4 + 2];
            v.w += bias[4 * c4 + 3];
            if (act) {
                v.x = (v.x > 0.f) ? v.x : SLOPE_ * v.x;
                v.y = (v.y > 0.f) ? v.y : SLOPE_ * v.y;
                v.z = (v.z > 0.f) ? v.z : SLOPE_ * v.z;
                v.w = (v.w > 0.f) ? v.w : SLOPE_ * v.w;
            }
            const int py = by + (p >> 4);
            const int px = bx + (p & 15);
            *(float4*)(out + ((size_t)b * HW_ + py * W_ + px) * 64 + 4 * c4) = v;
        }
    } else {
        const float* bs = bias + slice * NOUT;
#pragma unroll 1
        for (int i = tid; i < NOUT * 128; i += 256) {
            const int c = i >> 7;
            const int p = i & 127;
            float v = smf[p * LDO + c] + bs[c];
            if (act) v = (v > 0.f) ? v : SLOPE_ * v;
            const int py = by + (p >> 4);
            const int px = bx + (p & 15);
            out[((size_t)b * OC_ + slice * NOUT + c) * HW_ + py * W_ + px] = v;
        }
    }
}

// ---------------------------------------------------------------------------
// Modulated deformable conv (DCNv2Pack apply) — NHWC gathers + FFMA2.
// (verified in R6)
// ---------------------------------------------------------------------------
__global__ __launch_bounds__(256, 2)
void dcn_k(const float* __restrict__ xT, const float* __restrict__ co,
           const float* __restrict__ wgt, const float* __restrict__ bias,
           float* __restrict__ out, float* __restrict__ outT, int act)
{
    __shared__ float s_wg[KK_ * 8 * 64];

    const int tid = threadIdx.x;
    const int b   = blockIdx.z;
    const int y   = blockIdx.y * 16 + (tid >> 4);
    const int x   = blockIdx.x * 16 + (tid & 15);

    uint64_t acc2[32];
#pragma unroll
    for (int j = 0; j < 32; ++j) acc2[j] = 0ull;

    const float* cob = co + (size_t)b * OC_ * HW_;
    const float* xb  = xT + (size_t)b * HW_ * 64;
    const int pix = y * W_ + x;

#pragma unroll 1
    for (int g = 0; g < DG_; ++g) {
        __syncthreads();
#pragma unroll 1
        for (int i = tid; i < KK_ * 8 * 64; i += 256) {
            const int o = i & 63;
            const int r = i >> 6;
            const int k = r >> 3;
            const int c = r & 7;
            s_wg[i] = wgt[((size_t)o * 64 + g * 8 + c) * KK_ + k];
        }
        __syncthreads();

#pragma unroll 1
        for (int k = 0; k < KK_; ++k) {
            const float offy = cob[(size_t)(g * 18 + 2 * k    ) * HW_ + pix];
            const float offx = cob[(size_t)(g * 18 + 2 * k + 1) * HW_ + pix];
            const float ml   = cob[(size_t)(144 + g * 9 + k   ) * HW_ + pix];
            const float m    = 1.f / (1.f + __expf(-ml));

            const float py = (float)y + (float)(k / 3 - 1) + offy;
            const float px = (float)x + (float)(k % 3 - 1) + offx;
            const float y0f = floorf(py), x0f = floorf(px);
            const float ly = py - y0f,  lx = px - x0f;
            const int y0 = (int)y0f,    x0 = (int)x0f;

            const float w00 = (1.f - ly) * (1.f - lx) * m;
            const float w01 = (1.f - ly) * lx * m;
            const float w10 = ly * (1.f - lx) * m;
            const float w11 = ly * lx * m;

            const bool iy0 = (y0 >= 0)     && (y0 < H_);
            const bool iy1 = (y0 + 1 >= 0) && (y0 + 1 < H_);
            const bool ix0 = (x0 >= 0)     && (x0 < W_);
            const bool ix1 = (x0 + 1 >= 0) && (x0 + 1 < W_);

            float4 c00a = {0,0,0,0}, c00b = {0,0,0,0};
            float4 c01a = {0,0,0,0}, c01b = {0,0,0,0};
            float4 c10a = {0,0,0,0}, c10b = {0,0,0,0};
            float4 c11a = {0,0,0,0}, c11b = {0,0,0,0};
            if (iy0 && ix0) {
                const float4* p = (const float4*)(xb + ((size_t)(y0 * W_ + x0)) * 64 + g * 8);
                c00a = __ldg(p); c00b = __ldg(p + 1);
            }
            if (iy0 && ix1) {
                const float4* p = (const float4*)(xb + ((size_t)(y0 * W_ + x0 + 1)) * 64 + g * 8);
                c01a = __ldg(p); c01b = __ldg(p + 1);
            }
            if (iy1 && ix0) {
                const float4* p = (const float4*)(xb + ((size_t)((y0 + 1) * W_ + x0)) * 64 + g * 8);
                c10a = __ldg(p); c10b = __ldg(p + 1);
            }
            if (iy1 && ix1) {
                const float4* p = (const float4*)(xb + ((size_t)((y0 + 1) * W_ + x0 + 1)) * 64 + g * 8);
                c11a = __ldg(p); c11b = __ldg(p + 1);
            }

            float s[8];
            s[0] = w00*c00a.x + w01*c01a.x + w10*c10a.x + w11*c11a.x;
            s[1] = w00*c00a.y + w01*c01a.y + w10*c10a.y + w11*c11a.y;
            s[2] = w00*c00a.z + w01*c01a.z + w10*c10a.z + w11*c11a.z;
            s[3] = w00*c00a.w + w01*c01a.w + w10*c10a.w + w11*c11a.w;
            s[4] = w00*c00b.x + w01*c01b.x + w10*c10b.x + w11*c11b.x;
            s[5] = w00*c00b.y + w01*c01b.y + w10*c10b.y + w11*c11b.y;
            s[6] = w00*c00b.z + w01*c01b.z + w10*c10b.z + w11*c11b.z;
            s[7] = w00*c00b.w + w01*c01b.w + w10*c10b.w + w11*c11b.w;

#pragma unroll
            for (int c = 0; c < 8; ++c) {
                const uint64_t s2 = dup2(s[c]);
                const ulonglong2* wr =
                    reinterpret_cast<const ulonglong2*>(&s_wg[(k * 8 + c) * 64]);
#pragma unroll
                for (int q = 0; q < 16; ++q) {
                    const ulonglong2 w4 = wr[q];
                    fma2(acc2[2 * q    ], s2, w4.x);
                    fma2(acc2[2 * q + 1], s2, w4.y);
                }
            }
        }
    }

    float v[64];
#pragma unroll
    for (int j = 0; j < 32; ++j) {
        float v0, v1;
        unpk2(acc2[j], v0, v1);
        v0 += bias[2 * j];
        v1 += bias[2 * j + 1];
        if (act) {
            v0 = (v0 > 0.f) ? v0 : SLOPE_ * v0;
            v1 = (v1 > 0.f) ? v1 : SLOPE_ * v1;
        }
        v[2 * j] = v0; v[2 * j + 1] = v1;
    }
    if (out) {
#pragma unroll
        for (int o = 0; o < 64; ++o)
            out[(((size_t)b * 64 + o) * H_ + y) * W_ + x] = v[o];
    }
    if (outT) {
        float4* dst = (float4*)(outT + ((size_t)b * HW_ + pix) * 64);
#pragma unroll
        for (int q = 0; q < 16; ++q)
            dst[q] = make_float4(v[4*q], v[4*q+1], v[4*q+2], v[4*q+3]);
    }
}

// ---------------------------------------------------------------------------
// Launch
// ---------------------------------------------------------------------------
extern "C" void kernel_launch(void* const* d_in, const int* in_sizes, int n_in,
                              void* d_out, int out_size)
{
    const float* nbr     = (const float*)d_in[0];
    const float* ref     = (const float*)d_in[1];
    const float* w_off1  = (const float*)d_in[2];
    const float* b_off1  = (const float*)d_in[3];
    const float* w_off2  = (const float*)d_in[4];
    const float* b_off2  = (const float*)d_in[5];
    const float* w_co    = (const float*)d_in[6];
    const float* b_co    = (const float*)d_in[7];
    const float* w_dcn   = (const float*)d_in[8];
    const float* b_dcn   = (const float*)d_in[9];
    const float* w_coff1 = (const float*)d_in[10];
    const float* b_coff1 = (const float*)d_in[11];
    const float* w_coff2 = (const float*)d_in[12];
    const float* b_coff2 = (const float*)d_in[13];
    const float* w_cco   = (const float*)d_in[14];
    const float* b_cco   = (const float*)d_in[15];
    const float* w_cdcn  = (const float*)d_in[16];
    const float* b_cdcn  = (const float*)d_in[17];
    float* outp = (float*)d_out;

    void *pA, *pB, *pCO, *pNT, *pRT, *pFT;
    void *pw1, *pw2, *pw3, *pw4, *pw5, *pw6;
    cudaGetSymbolAddress(&pA,  g_bufA);
    cudaGetSymbolAddress(&pB,  g_bufB);
    cudaGetSymbolAddress(&pCO, g_co);
    cudaGetSymbolAddress(&pNT, g_nbrT);
    cudaGetSymbolAddress(&pRT, g_refT);
    cudaGetSymbolAddress(&pFT, g_featT);
    cudaGetSymbolAddress(&pw1, g_wb1);
    cudaGetSymbolAddress(&pw2, g_wb2);
    cudaGetSymbolAddress(&pw3, g_wb3);
    cudaGetSymbolAddress(&pw4, g_wb4);
    cudaGetSymbolAddress(&pw5, g_wb5);
    cudaGetSymbolAddress(&pw6, g_wb6);
    float* bufA  = (float*)pA;
    float* bufB  = (float*)pB;
    float* bufCO = (float*)pCO;
    float* nbrT  = (float*)pNT;
    float* refT  = (float*)pRT;
    float* featT = (float*)pFT;

    // dynamic smem: B tap buffer + 2 A tiles
    constexpr int SM64 = 2 * 2 * 64 * 72 * 2 + 2 * 180 * 72 * 2;   // 36864+51840=88704
    constexpr int SM80 = 2 * 2 * 64 * 88 * 2 + 2 * 180 * 72 * 2;   // 45056+51840=96896
    cudaFuncSetAttribute(tconv_k<64, 64, 2>, cudaFuncAttributeMaxDynamicSharedMemorySize, SM64);
    cudaFuncSetAttribute(tconv_k<64, 64, 1>, cudaFuncAttributeMaxDynamicSharedMemorySize, SM64);
    cudaFuncSetAttribute(tconv_k<72, 80, 1>, cudaFuncAttributeMaxDynamicSharedMemorySize, SM80);

    const dim3 blk(256);
    const dim3 gT(HW_ / 64, B_);
    const dim3 gC(W_ / 16, H_ / 8, B_);          // (10, 20, 4)
    const dim3 gC3(W_ / 16, H_ / 8, B_ * 3);     // (10, 20, 12)
    const dim3 gD(W_ / 16, H_ / 16, B_);

    // transposes
    t_k<<<gT, blk>>>(nbr, nbrT);
    t_k<<<gT, blk>>>(ref, refT);

    // weight packing
    pack_k<<<dim3(72, 1), blk>>>(w_off1, 128, 64, 64, 72, 2, (__nv_bfloat16*)pw1);
    pack_k<<<dim3(36, 1), blk>>>(w_off2,  64, 64, 64, 72, 1, (__nv_bfloat16*)pw2);
    pack_k<<<dim3(18, 3), blk>>>(w_co,    64, 72, 80, 88, 1, (__nv_bfloat16*)pw3);
    pack_k<<<dim3(72, 1), blk>>>(w_coff1, 128, 64, 64, 72, 2, (__nv_bfloat16*)pw4);
    pack_k<<<dim3(36, 1), blk>>>(w_coff2,  64, 64, 64, 72, 1, (__nv_bfloat16*)pw5);
    pack_k<<<dim3(18, 3), blk>>>(w_cco,    64, 72, 80, 88, 1, (__nv_bfloat16*)pw6);

    // ---- first alignment stage ----
    tconv_k<64, 64, 2><<<gC, blk, SM64>>>(nbrT, refT, (__nv_bfloat16*)pw1, b_off1, bufA, 1);
    tconv_k<64, 64, 1><<<gC, blk, SM64>>>(bufA, nullptr, (__nv_bfloat16*)pw2, b_off2, bufB, 1);
    tconv_k<72, 80, 1><<<gC3, blk, SM80>>>(bufB, nullptr, (__nv_bfloat16*)pw3, b_co, bufCO, 0);
    dcn_k<<<gD, blk>>>(nbrT, bufCO, w_dcn, b_dcn, nullptr, featT, 1);

    // ---- cascade stage ----
    tconv_k<64, 64, 2><<<gC, blk, SM64>>>(featT, refT, (__nv_bfloat16*)pw4, b_coff1, bufA, 1);
    tconv_k<64, 64, 1><<<gC, blk, SM64>>>(bufA, nullptr, (__nv_bfloat16*)pw5, b_coff2, bufB, 1);
    tconv_k<72, 80, 1><<<gC3, blk, SM80>>>(bufB, nullptr, (__nv_bfloat16*)pw6, b_cco, bufCO, 0);
    dcn_k<<<gD, blk>>>(featT, bufCO, w_cdcn, b_cdcn, outp, nullptr, 1);
}